// round 7
// baseline (speedup 1.0000x reference)
#include <cuda_runtime.h>
#include <cstdint>

#define BATCH 2
#define SEQ   2048
#define DM    1024
#define NH    16
#define DH    64
#define MTOT  (BATCH * SEQ)   // 4096

#define BM 128
#define BN 128
#define BK 16
#define A_LD (BK + 4)    // 20 floats/row, conflict-free A-frag LDS
#define B_LD (BN + 8)    // 136 floats/row, conflict-free B-frag LDS

// attention tiles
#define QT 128
#define QT_LD 132   // 128 + 4 pad
#define KV_LD 68    // 64 + 4 pad

// scratch (allocation-free rule: __device__ globals)
__device__ float g_Q[BATCH * NH * SEQ * DH];
__device__ float g_K[BATCH * NH * SEQ * DH];
__device__ float g_V[BATCH * NH * SEQ * DH];
__device__ float g_H[MTOT * DM];

// ---------------------------------------------------------------------------
// cp.async helpers
// ---------------------------------------------------------------------------
__device__ __forceinline__ uint32_t smaddr(const void* p) {
    return (uint32_t)__cvta_generic_to_shared(p);
}
__device__ __forceinline__ void cpa16(uint32_t s, const void* g) {
    asm volatile("cp.async.cg.shared.global [%0], [%1], 16;" :: "r"(s), "l"(g));
}
__device__ __forceinline__ void cpa_commit() {
    asm volatile("cp.async.commit_group;");
}
__device__ __forceinline__ void cpa_wait0() {
    asm volatile("cp.async.wait_group 0;");
}

// ---------------------------------------------------------------------------
// tf32 mma helpers
// ---------------------------------------------------------------------------
__device__ __forceinline__ void split_tf32(float v, uint32_t& hi, uint32_t& lo) {
    uint32_t h;
    asm("cvt.rna.tf32.f32 %0, %1;" : "=r"(h) : "f"(v));
    float r = v - __uint_as_float(h);
    asm("cvt.rna.tf32.f32 %0, %1;" : "=r"(lo) : "f"(r));
    hi = h;
}
__device__ __forceinline__ void mma_tf32(float d[4], const uint32_t a[4],
                                         const uint32_t b[2]) {
    asm volatile(
        "mma.sync.aligned.m16n8k8.row.col.f32.tf32.tf32.f32 "
        "{%0,%1,%2,%3}, {%4,%5,%6,%7}, {%8,%9}, {%0,%1,%2,%3};"
        : "+f"(d[0]), "+f"(d[1]), "+f"(d[2]), "+f"(d[3])
        : "r"(a[0]), "r"(a[1]), "r"(a[2]), "r"(a[3]), "r"(b[0]), "r"(b[1]));
}

// ---------------------------------------------------------------------------
// TF32 tensor-core GEMM core (3xTF32 compensated, fp32-accurate).
// CTA 128x128, 8 warps in 2(m) x 4(n); warp tile 64x32 = 4x4 m16n8k8.
// A staged row-major [m][K] (pad 4), B staged [k][N] (pad 8), cp.async both.
// ---------------------------------------------------------------------------
__device__ __forceinline__ void mma_gemm_tile(const float* __restrict__ A,
                                              const float* __restrict__ B,
                                              int m0, int n0, int lda, int ldb,
                                              float acc[4][4][4]) {
    __shared__ __align__(16) float As[2][BM][A_LD];
    __shared__ __align__(16) float Bs[2][BK][B_LD];

    const int tid  = threadIdx.x;
    const int lane = tid & 31;
    const int warp = tid >> 5;
    const int wm   = warp & 1;        // 0..1
    const int wn   = warp >> 1;       // 0..3

    // loader coords
    const int ar = tid >> 1;          // 0..127
    const int ac = (tid & 1) << 3;    // 0 or 8
    const int br = tid >> 4;          // 0..15
    const int bc = (tid & 15) << 3;   // 0..120

    const float* Ap = A + (size_t)(m0 + ar) * lda + ac;
    const float* Bp = B + (size_t)br * ldb + n0 + bc;

    // fragment coords
    const int frow = lane >> 2;       // 0..7
    const int fk   = lane & 3;        // 0..3
    const int abase = wm * 64 + frow;
    const int bbase = wn * 32 + frow;

    // prologue: tile 0
    cpa16(smaddr(&As[0][ar][ac]),     Ap);
    cpa16(smaddr(&As[0][ar][ac + 4]), Ap + 4);
    cpa16(smaddr(&Bs[0][br][bc]),     Bp);
    cpa16(smaddr(&Bs[0][br][bc + 4]), Bp + 4);
    cpa_commit();
    cpa_wait0();
    __syncthreads();

    int buf = 0;
    for (int kt = BK; kt <= DM; kt += BK) {
        const bool more = (kt < DM);
        if (more) {
            const float* ap = Ap + kt;
            const float* bp = Bp + (size_t)kt * ldb;
            cpa16(smaddr(&As[buf ^ 1][ar][ac]),     ap);
            cpa16(smaddr(&As[buf ^ 1][ar][ac + 4]), ap + 4);
            cpa16(smaddr(&Bs[buf ^ 1][br][bc]),     bp);
            cpa16(smaddr(&Bs[buf ^ 1][br][bc + 4]), bp + 4);
            cpa_commit();
        }
        #pragma unroll
        for (int ks = 0; ks < BK / 8; ks++) {
            const int k0 = ks * 8 + fk;
            // B fragments (hi/lo) for all 4 n-tiles
            uint32_t bh[4][2], bl[4][2];
            #pragma unroll
            for (int nt = 0; nt < 4; nt++) {
                float b0 = Bs[buf][k0][bbase + nt * 8];
                float b1 = Bs[buf][k0 + 4][bbase + nt * 8];
                split_tf32(b0, bh[nt][0], bl[nt][0]);
                split_tf32(b1, bh[nt][1], bl[nt][1]);
            }
            #pragma unroll
            for (int mt = 0; mt < 4; mt++) {
                const int r0 = abase + mt * 16;
                float a0 = As[buf][r0][k0];
                float a1 = As[buf][r0 + 8][k0];
                float a2 = As[buf][r0][k0 + 4];
                float a3 = As[buf][r0 + 8][k0 + 4];
                uint32_t ah[4], al[4];
                split_tf32(a0, ah[0], al[0]);
                split_tf32(a1, ah[1], al[1]);
                split_tf32(a2, ah[2], al[2]);
                split_tf32(a3, ah[3], al[3]);
                #pragma unroll
                for (int nt = 0; nt < 4; nt++) {
                    mma_tf32(acc[mt][nt], ah, bh[nt]);
                    mma_tf32(acc[mt][nt], al, bh[nt]);
                    mma_tf32(acc[mt][nt], ah, bl[nt]);
                }
            }
        }
        if (more) {
            buf ^= 1;
            cpa_wait0();
            __syncthreads();
        }
    }
}

// ---------------------------------------------------------------------------
// QKV projections: y = x @ W + b, scattered to [B, H, S, Dh]
// ---------------------------------------------------------------------------
__global__ __launch_bounds__(256, 2)
void qkv_gemm_kernel(const float* __restrict__ x,
                     const float* __restrict__ Wq, const float* __restrict__ bq,
                     const float* __restrict__ Wk, const float* __restrict__ bk,
                     const float* __restrict__ Wv, const float* __restrict__ bv) {
    const int m0 = blockIdx.y << 7;
    const int n0 = blockIdx.x << 7;
    const int which = blockIdx.z;
    const float* W    = (which == 0) ? Wq : (which == 1) ? Wk : Wv;
    const float* bias = (which == 0) ? bq : (which == 1) ? bk : bv;
    float* out        = (which == 0) ? g_Q : (which == 1) ? g_K : g_V;

    float acc[4][4][4] = {};
    mma_gemm_tile(x, W, m0, n0, DM, DM, acc);

    const int lane = threadIdx.x & 31;
    const int warp = threadIdx.x >> 5;
    const int wm   = warp & 1;
    const int wn   = warp >> 1;

    #pragma unroll
    for (int mt = 0; mt < 4; mt++) {
        #pragma unroll
        for (int nt = 0; nt < 4; nt++) {
            const int n = n0 + wn * 32 + nt * 8 + ((lane & 3) << 1);
            const int h = n >> 6;
            const int d = n & 63;
            const float bn0 = bias[n], bn1 = bias[n + 1];
            #pragma unroll
            for (int half = 0; half < 2; half++) {
                const int m = m0 + wm * 64 + mt * 16 + (lane >> 2) + half * 8;
                const int b = m >> 11;
                const int s = m & (SEQ - 1);
                float2 v = make_float2(acc[mt][nt][half * 2 + 0] + bn0,
                                       acc[mt][nt][half * 2 + 1] + bn1);
                *(float2*)&out[((size_t)((b * NH + h) * SEQ + s) << 6) + d] = v;
            }
        }
    }
}

// ---------------------------------------------------------------------------
// Output projection: out = g_H @ Wo + bo
// ---------------------------------------------------------------------------
__global__ __launch_bounds__(256, 2)
void out_gemm_kernel(const float* __restrict__ Wo, const float* __restrict__ bo,
                     float* __restrict__ out) {
    const int m0 = blockIdx.y << 7;
    const int n0 = blockIdx.x << 7;

    float acc[4][4][4] = {};
    mma_gemm_tile(g_H, Wo, m0, n0, DM, DM, acc);

    const int lane = threadIdx.x & 31;
    const int warp = threadIdx.x >> 5;
    const int wm   = warp & 1;
    const int wn   = warp >> 1;

    #pragma unroll
    for (int mt = 0; mt < 4; mt++) {
        #pragma unroll
        for (int nt = 0; nt < 4; nt++) {
            const int n = n0 + wn * 32 + nt * 8 + ((lane & 3) << 1);
            const float bn0 = bo[n], bn1 = bo[n + 1];
            #pragma unroll
            for (int half = 0; half < 2; half++) {
                const int m = m0 + wm * 64 + mt * 16 + (lane >> 2) + half * 8;
                float2 v = make_float2(acc[mt][nt][half * 2 + 0] + bn0,
                                       acc[mt][nt][half * 2 + 1] + bn1);
                *(float2*)&out[(size_t)m * DM + n] = v;
            }
        }
    }
}

// ---------------------------------------------------------------------------
// Causal flash attention: q-tile 128 x k-tile 64, 256 threads. (unchanged R4)
// ---------------------------------------------------------------------------
__global__ __launch_bounds__(256, 2)
void attn_kernel() {
    extern __shared__ float smf[];
    float* Qt = smf;                   // [64][QT_LD]  Qt[d][r]
    float* Kt = Qt + 64 * QT_LD;       // [64][KV_LD]  Kt[d][c]
    float* Vs = Kt + 64 * KV_LD;       // [64][KV_LD]  Vs[k][d]
    float* Ps = Vs + 64 * KV_LD;       // [128][KV_LD] Ps[r][k]

    const int qt = (gridDim.x - 1) - blockIdx.x;  // heavy tiles first
    const int bh = blockIdx.y;
    const int b  = bh / NH;
    const int h  = bh % NH;
    const int qb = qt * QT;

    const float* Qg = g_Q + (size_t)(bh * SEQ + qb) * DH;
    const float* Kg = g_K + (size_t)bh * SEQ * DH;
    const float* Vg = g_V + (size_t)bh * SEQ * DH;

    const int tid = threadIdx.x;
    const int ty  = tid >> 4;
    const int tx  = tid & 15;

    {
        const int r  = tid >> 1;
        const int c0 = (tid & 1) << 5;
        const float* qp = Qg + (size_t)r * DH + c0;
        #pragma unroll
        for (int q = 0; q < 32; q += 4) {
            float4 v = *(const float4*)(qp + q);
            Qt[(c0 + q + 0) * QT_LD + r] = v.x;
            Qt[(c0 + q + 1) * QT_LD + r] = v.y;
            Qt[(c0 + q + 2) * QT_LD + r] = v.z;
            Qt[(c0 + q + 3) * QT_LD + r] = v.w;
        }
    }

    float O[8][4];
    float mrun[8], lrun[8];
    #pragma unroll
    for (int i = 0; i < 8; i++) {
        mrun[i] = -1e30f; lrun[i] = 0.f;
        #pragma unroll
        for (int j = 0; j < 4; j++) O[i][j] = 0.f;
    }
    const float scale = 0.125f;
    const int ktmax = 2 * qt + 1;

    for (int kt = 0; kt <= ktmax; kt++) {
        __syncthreads();
        {
            const int lr = tid >> 2;
            const int c0 = (tid & 3) << 4;
            const float* kp = Kg + (size_t)((kt << 6) + lr) * DH + c0;
            const float* vp = Vg + (size_t)((kt << 6) + lr) * DH + c0;
            #pragma unroll
            for (int q = 0; q < 16; q += 4) {
                float4 kv = *(const float4*)(kp + q);
                Kt[(c0 + q + 0) * KV_LD + lr] = kv.x;
                Kt[(c0 + q + 1) * KV_LD + lr] = kv.y;
                Kt[(c0 + q + 2) * KV_LD + lr] = kv.z;
                Kt[(c0 + q + 3) * KV_LD + lr] = kv.w;
                *(float4*)&Vs[lr * KV_LD + c0 + q] = *(const float4*)(vp + q);
            }
        }
        __syncthreads();

        float s[8][4] = {};
        #pragma unroll 8
        for (int d = 0; d < 64; d++) {
            float q[8];
            *(float4*)&q[0] = *(const float4*)&Qt[d * QT_LD + (ty << 3)];
            *(float4*)&q[4] = *(const float4*)&Qt[d * QT_LD + (ty << 3) + 4];
            float4 kv = *(const float4*)&Kt[d * KV_LD + (tx << 2)];
            #pragma unroll
            for (int i = 0; i < 8; i++) {
                s[i][0] = fmaf(q[i], kv.x, s[i][0]);
                s[i][1] = fmaf(q[i], kv.y, s[i][1]);
                s[i][2] = fmaf(q[i], kv.z, s[i][2]);
                s[i][3] = fmaf(q[i], kv.w, s[i][3]);
            }
        }

        if (kt >= 2 * qt) {
            #pragma unroll
            for (int i = 0; i < 8; i++) {
                const int qg = qb + (ty << 3) + i;
                #pragma unroll
                for (int j = 0; j < 4; j++) {
                    const int kg = (kt << 6) + (tx << 2) + j;
                    s[i][j] = (kg <= qg) ? s[i][j] * scale : -1e30f;
                }
            }
        } else {
            #pragma unroll
            for (int i = 0; i < 8; i++)
                #pragma unroll
                for (int j = 0; j < 4; j++) s[i][j] *= scale;
        }

        #pragma unroll
        for (int i = 0; i < 8; i++) {
            float m = fmaxf(fmaxf(s[i][0], s[i][1]), fmaxf(s[i][2], s[i][3]));
            m = fmaxf(m, __shfl_xor_sync(0xffffffffu, m, 1));
            m = fmaxf(m, __shfl_xor_sync(0xffffffffu, m, 2));
            m = fmaxf(m, __shfl_xor_sync(0xffffffffu, m, 4));
            m = fmaxf(m, __shfl_xor_sync(0xffffffffu, m, 8));
            const float mnew  = fmaxf(mrun[i], m);
            const float alpha = __expf(mrun[i] - mnew);
            float l = 0.f;
            #pragma unroll
            for (int j = 0; j < 4; j++) {
                s[i][j] = __expf(s[i][j] - mnew);
                l += s[i][j];
            }
            l += __shfl_xor_sync(0xffffffffu, l, 1);
            l += __shfl_xor_sync(0xffffffffu, l, 2);
            l += __shfl_xor_sync(0xffffffffu, l, 4);
            l += __shfl_xor_sync(0xffffffffu, l, 8);
            lrun[i] = lrun[i] * alpha + l;
            mrun[i] = mnew;
            #pragma unroll
            for (int j = 0; j < 4; j++) O[i][j] *= alpha;
            *(float4*)&Ps[((ty << 3) + i) * KV_LD + (tx << 2)] =
                make_float4(s[i][0], s[i][1], s[i][2], s[i][3]);
        }
        __syncwarp();

        #pragma unroll 2
        for (int k4 = 0; k4 < 64; k4 += 4) {
            float4 p[8];
            #pragma unroll
            for (int i = 0; i < 8; i++)
                p[i] = *(const float4*)&Ps[((ty << 3) + i) * KV_LD + k4];
            #pragma unroll
            for (int t = 0; t < 4; t++) {
                float4 v = *(const float4*)&Vs[(k4 + t) * KV_LD + (tx << 2)];
                #pragma unroll
                for (int i = 0; i < 8; i++) {
                    const float pv = (t == 0) ? p[i].x : (t == 1) ? p[i].y
                                   : (t == 2) ? p[i].z : p[i].w;
                    O[i][0] = fmaf(pv, v.x, O[i][0]);
                    O[i][1] = fmaf(pv, v.y, O[i][1]);
                    O[i][2] = fmaf(pv, v.z, O[i][2]);
                    O[i][3] = fmaf(pv, v.w, O[i][3]);
                }
            }
        }
    }

    #pragma unroll
    for (int i = 0; i < 8; i++) {
        const float inv = 1.0f / lrun[i];
        float* outp = g_H + (size_t)(b * SEQ + qb + (ty << 3) + i) * DM
                          + h * DH + (tx << 2);
        *(float4*)outp = make_float4(O[i][0] * inv, O[i][1] * inv,
                                     O[i][2] * inv, O[i][3] * inv);
    }
}

// ---------------------------------------------------------------------------
extern "C" void kernel_launch(void* const* d_in, const int* in_sizes, int n_in,
                              void* d_out, int out_size) {
    const float* x  = (const float*)d_in[0];
    const float* Wq = (const float*)d_in[1];
    const float* bq = (const float*)d_in[2];
    const float* Wk = (const float*)d_in[3];
    const float* bk = (const float*)d_in[4];
    const float* Wv = (const float*)d_in[5];
    const float* bv = (const float*)d_in[6];
    const float* Wo = (const float*)d_in[7];
    const float* bo = (const float*)d_in[8];
    float* out = (float*)d_out;

    // 1. QKV projections (tf32 tensor cores, 3xTF32)
    dim3 gq(DM / BN, MTOT / BM, 3);
    qkv_gemm_kernel<<<gq, 256>>>(x, Wq, bq, Wk, bk, Wv, bv);

    // 2. causal flash attention
    const size_t smem = (size_t)(64 * QT_LD + 2 * 64 * KV_LD + 128 * KV_LD)
                        * sizeof(float);
    cudaFuncSetAttribute(attn_kernel, cudaFuncAttributeMaxDynamicSharedMemorySize,
                         (int)smem);
    attn_kernel<<<dim3(SEQ / QT, BATCH * NH), 256, smem>>>();

    // 3. output projection (tf32 tensor cores, 3xTF32)
    out_gemm_kernel<<<dim3(DM / BN, MTOT / BM), 256>>>(Wo, bo, out);
}

// round 8
// speedup vs baseline: 1.1859x; 1.1859x over previous
#include <cuda_runtime.h>
#include <cuda_bf16.h>
#include <cstdint>

typedef __nv_bfloat16 bf16;
typedef uint32_t u32;

#define BATCH 2
#define SEQ   2048
#define DM    1024
#define NH    16
#define DH    64
#define MTOT  (BATCH * SEQ)   // 4096

// attention tiles (fp32 FFMA path, R5 structure)
#define QT 128
#define QT_LD 132
#define KV_LD 68

// GEMM smem: 4 tiles (Ah,Al,Bh,Bl) x double buffer x [128][20] u32
#define TROW 20
#define TBUF (128 * TROW)
#define GEMM_SMEM (4 * 2 * TBUF * 4)

// ---------------------------------------------------------------------------
// device scratch (allocation-free rule)
// ---------------------------------------------------------------------------
__device__ bf16 g_xh[MTOT * DM], g_xl[MTOT * DM];           // x hi/lo [m][k]
__device__ bf16 g_Wh[4 * DM * DM], g_Wl[4 * DM * DM];       // W^T hi/lo [w][n][k]
__device__ float g_Q[MTOT * DM];                            // [bh][s][d]
__device__ float g_K[MTOT * DM];
__device__ float g_V[MTOT * DM];
__device__ bf16 g_Hh[MTOT * DM], g_Hl[MTOT * DM];           // attn out hi/lo [m][k]

// ---------------------------------------------------------------------------
// helpers
// ---------------------------------------------------------------------------
__device__ __forceinline__ u32 smaddr(const void* p) {
    return (u32)__cvta_generic_to_shared(p);
}
__device__ __forceinline__ void cpa16(u32 s, const void* g) {
    asm volatile("cp.async.cg.shared.global [%0], [%1], 16;" :: "r"(s), "l"(g));
}
__device__ __forceinline__ void cpa_commit() { asm volatile("cp.async.commit_group;"); }
__device__ __forceinline__ void cpa_wait0()  { asm volatile("cp.async.wait_group 0;"); }

__device__ __forceinline__ void bsplit(float v, bf16& h, bf16& l) {
    h = __float2bfloat16(v);
    l = __float2bfloat16(v - __bfloat162float(h));
}
__device__ __forceinline__ u32 bpack(bf16 a, bf16 b) {
    __nv_bfloat162 t = __halves2bfloat162(a, b);
    return *reinterpret_cast<u32*>(&t);
}
__device__ __forceinline__ void mma_bf16(float d[4], const u32 a[4], const u32 b[2]) {
    asm volatile(
        "mma.sync.aligned.m16n8k16.row.col.f32.bf16.bf16.f32 "
        "{%0,%1,%2,%3}, {%4,%5,%6,%7}, {%8,%9}, {%0,%1,%2,%3};"
        : "+f"(d[0]), "+f"(d[1]), "+f"(d[2]), "+f"(d[3])
        : "r"(a[0]), "r"(a[1]), "r"(a[2]), "r"(a[3]), "r"(b[0]), "r"(b[1]));
}

// fast 2^t on the FMA pipe (t <= ~0), |rel err| ~1e-7
__device__ __forceinline__ float fexp2(float t) {
    t = fmaxf(t, -124.0f);
    float k = t + 12582912.0f;                 // round to nearest int
    int   n = __float_as_int(k) - 0x4B400000;
    float f = t - (k - 12582912.0f);           // f in [-0.5, 0.5]
    float p = 1.5403530393e-4f;
    p = fmaf(p, f, 1.3333558146e-3f);
    p = fmaf(p, f, 9.6181291076e-3f);
    p = fmaf(p, f, 5.5504108665e-2f);
    p = fmaf(p, f, 2.4022650696e-1f);
    p = fmaf(p, f, 6.9314718056e-1f);
    p = fmaf(p, f, 1.0f);
    return __int_as_float(__float_as_int(p) + (n << 23));
}

// ---------------------------------------------------------------------------
// prologue: split x; transpose + split W
// ---------------------------------------------------------------------------
__global__ __launch_bounds__(256)
void split_x_kernel(const float* __restrict__ x) {
    int i = blockIdx.x * 256 + threadIdx.x;
    bf16 h, l; bsplit(x[i], h, l);
    g_xh[i] = h; g_xl[i] = l;
}

__global__ __launch_bounds__(256)
void split_w_kernel(const float* __restrict__ Wq, const float* __restrict__ Wk,
                    const float* __restrict__ Wv, const float* __restrict__ Wo) {
    __shared__ float t[32][33];
    const int z = blockIdx.z;
    const float* W = (z == 0) ? Wq : (z == 1) ? Wk : (z == 2) ? Wv : Wo;
    bf16* oh = g_Wh + (size_t)z * DM * DM;
    bf16* ol = g_Wl + (size_t)z * DM * DM;
    const int k0 = blockIdx.x << 5, n0 = blockIdx.y << 5;
    const int tx = threadIdx.x & 31, ty = threadIdx.x >> 5;  // 32 x 8
    #pragma unroll
    for (int i = 0; i < 32; i += 8)
        t[ty + i][tx] = W[(size_t)(k0 + ty + i) * DM + n0 + tx];
    __syncthreads();
    #pragma unroll
    for (int i = 0; i < 32; i += 8) {
        bf16 h, l; bsplit(t[tx][ty + i], h, l);
        oh[(size_t)(n0 + ty + i) * DM + k0 + tx] = h;
        ol[(size_t)(n0 + ty + i) * DM + k0 + tx] = l;
    }
}

// ---------------------------------------------------------------------------
// bf16x3 GEMM core: CTA 128x128, BK=32 (2 x k16 steps), 8 warps (2m x 4n),
// warp tile 64x32. A [m][k] hi/lo, B = W^T [n][k] hi/lo. Pure LDS+MMA loop.
// ---------------------------------------------------------------------------
__device__ __forceinline__ void bgemm_core(const bf16* __restrict__ Ah,
                                           const bf16* __restrict__ Al,
                                           const bf16* __restrict__ Bh,
                                           const bf16* __restrict__ Bl,
                                           int m0, int n0,
                                           float acc[4][4][4], char* sm) {
    u32* AsH = (u32*)sm;            // [2][128][TROW]
    u32* AsL = AsH + 2 * TBUF;
    u32* BsH = AsL + 2 * TBUF;
    u32* BsL = BsH + 2 * TBUF;

    const int tid  = threadIdx.x;
    const int lane = tid & 31, warp = tid >> 5;
    const int wm = warp & 1, wn = warp >> 1;
    const int g = lane >> 2, tig = lane & 3;
    const int lr = tid >> 1;              // loader row 0..127
    const int lc = (tid & 1) << 3;        // u32 col 0 or 8

    const bf16* pAh = Ah + (size_t)(m0 + lr) * DM + (lc << 1);
    const bf16* pAl = Al + (size_t)(m0 + lr) * DM + (lc << 1);
    const bf16* pBh = Bh + (size_t)(n0 + lr) * DM + (lc << 1);
    const bf16* pBl = Bl + (size_t)(n0 + lr) * DM + (lc << 1);
    const u32 dst0 = lr * TROW + lc;

#define LD_TILE(bufv, koff) do {                                          \
    u32 d_ = (bufv) * TBUF + dst0;                                        \
    cpa16(smaddr(AsH + d_),     pAh + (koff));                            \
    cpa16(smaddr(AsH + d_ + 4), pAh + (koff) + 8);                        \
    cpa16(smaddr(AsL + d_),     pAl + (koff));                            \
    cpa16(smaddr(AsL + d_ + 4), pAl + (koff) + 8);                        \
    cpa16(smaddr(BsH + d_),     pBh + (koff));                            \
    cpa16(smaddr(BsH + d_ + 4), pBh + (koff) + 8);                        \
    cpa16(smaddr(BsL + d_),     pBl + (koff));                            \
    cpa16(smaddr(BsL + d_ + 4), pBl + (koff) + 8);                        \
    cpa_commit(); } while (0)

    LD_TILE(0, 0);
    cpa_wait0();
    __syncthreads();

    int buf = 0;
    for (int kt = 32; kt <= DM; kt += 32) {
        const bool more = (kt < DM);
        if (more) LD_TILE(buf ^ 1, kt);

        #pragma unroll
        for (int ks = 0; ks < 2; ks++) {
            const int kc = ks * 8 + tig;
            u32 bhf[4][2], blf[4][2];
            #pragma unroll
            for (int nt = 0; nt < 4; nt++) {
                const int off = buf * TBUF + (wn * 32 + nt * 8 + g) * TROW;
                bhf[nt][0] = BsH[off + kc];  bhf[nt][1] = BsH[off + kc + 4];
                blf[nt][0] = BsL[off + kc];  blf[nt][1] = BsL[off + kc + 4];
            }
            #pragma unroll
            for (int mt = 0; mt < 4; mt++) {
                const int o1 = buf * TBUF + (wm * 64 + mt * 16 + g) * TROW;
                const int o2 = o1 + 8 * TROW;
                u32 ah[4] = {AsH[o1 + kc], AsH[o2 + kc],
                             AsH[o1 + kc + 4], AsH[o2 + kc + 4]};
                u32 al[4] = {AsL[o1 + kc], AsL[o2 + kc],
                             AsL[o1 + kc + 4], AsL[o2 + kc + 4]};
                #pragma unroll
                for (int nt = 0; nt < 4; nt++) {
                    mma_bf16(acc[mt][nt], ah, bhf[nt]);
                    mma_bf16(acc[mt][nt], al, bhf[nt]);
                    mma_bf16(acc[mt][nt], ah, blf[nt]);
                }
            }
        }
        if (more) {
            cpa_wait0();
            __syncthreads();
            buf ^= 1;
        }
    }
#undef LD_TILE
}

// ---------------------------------------------------------------------------
// QKV projections -> fp32 Q,K,V in [B,H,S,Dh]
// ---------------------------------------------------------------------------
__global__ __launch_bounds__(256, 2)
void qkv_gemm_kernel(const float* __restrict__ bq, const float* __restrict__ bk,
                     const float* __restrict__ bv) {
    extern __shared__ char sm[];
    const int m0 = blockIdx.y << 7;
    const int n0 = blockIdx.x << 7;
    const int which = blockIdx.z;
    const bf16* Bh = g_Wh + (size_t)which * DM * DM;
    const bf16* Bl = g_Wl + (size_t)which * DM * DM;
    const float* bias = (which == 0) ? bq : (which == 1) ? bk : bv;
    float* out = (which == 0) ? g_Q : (which == 1) ? g_K : g_V;

    float acc[4][4][4] = {};
    bgemm_core(g_xh, g_xl, Bh, Bl, m0, n0, acc, sm);

    const int lane = threadIdx.x & 31;
    const int warp = threadIdx.x >> 5;
    const int wm = warp & 1, wn = warp >> 1;

    #pragma unroll
    for (int mt = 0; mt < 4; mt++) {
        #pragma unroll
        for (int nt = 0; nt < 4; nt++) {
            const int n = n0 + wn * 32 + nt * 8 + ((lane & 3) << 1);
            const int h = n >> 6;
            const int d = n & 63;
            const float bn0 = bias[n], bn1 = bias[n + 1];
            #pragma unroll
            for (int half = 0; half < 2; half++) {
                const int m = m0 + wm * 64 + mt * 16 + (lane >> 2) + half * 8;
                const int b = m >> 11;
                const int s = m & (SEQ - 1);
                float2 v = make_float2(acc[mt][nt][half * 2 + 0] + bn0,
                                       acc[mt][nt][half * 2 + 1] + bn1);
                *(float2*)&out[((size_t)((b * NH + h) * SEQ + s) << 6) + d] = v;
            }
        }
    }
}

// ---------------------------------------------------------------------------
// Output projection: out = H @ Wo + bo (H pre-split by attention epilogue)
// ---------------------------------------------------------------------------
__global__ __launch_bounds__(256, 2)
void out_gemm_kernel(const float* __restrict__ bo, float* __restrict__ out) {
    extern __shared__ char sm[];
    const int m0 = blockIdx.y << 7;
    const int n0 = blockIdx.x << 7;
    const bf16* Bh = g_Wh + (size_t)3 * DM * DM;
    const bf16* Bl = g_Wl + (size_t)3 * DM * DM;

    float acc[4][4][4] = {};
    bgemm_core(g_Hh, g_Hl, Bh, Bl, m0, n0, acc, sm);

    const int lane = threadIdx.x & 31;
    const int warp = threadIdx.x >> 5;
    const int wm = warp & 1, wn = warp >> 1;

    #pragma unroll
    for (int mt = 0; mt < 4; mt++) {
        #pragma unroll
        for (int nt = 0; nt < 4; nt++) {
            const int n = n0 + wn * 32 + nt * 8 + ((lane & 3) << 1);
            const float bn0 = bo[n], bn1 = bo[n + 1];
            #pragma unroll
            for (int half = 0; half < 2; half++) {
                const int m = m0 + wm * 64 + mt * 16 + (lane >> 2) + half * 8;
                float2 v = make_float2(acc[mt][nt][half * 2 + 0] + bn0,
                                       acc[mt][nt][half * 2 + 1] + bn1);
                *(float2*)&out[(size_t)m * DM + n] = v;
            }
        }
    }
}

// ---------------------------------------------------------------------------
// Causal flash attention (R5 structure; exp on FMA pipe; split-bf16 epilogue)
// ---------------------------------------------------------------------------
__global__ __launch_bounds__(256, 2)
void attn_kernel() {
    extern __shared__ float smf[];
    float* Qt = smf;                   // [64][QT_LD]
    float* Kt = Qt + 64 * QT_LD;       // [64][KV_LD]
    float* Vs = Kt + 64 * KV_LD;       // [64][KV_LD]
    float* Ps = Vs + 64 * KV_LD;       // [128][KV_LD]

    const int qt = (gridDim.x - 1) - blockIdx.x;
    const int bh = blockIdx.y;
    const int b  = bh / NH;
    const int h  = bh % NH;
    const int qb = qt * QT;

    const float* Qg = g_Q + (size_t)(bh * SEQ + qb) * DH;
    const float* Kg = g_K + (size_t)bh * SEQ * DH;
    const float* Vg = g_V + (size_t)bh * SEQ * DH;

    const int tid = threadIdx.x;
    const int ty  = tid >> 4;
    const int tx  = tid & 15;

    {
        const int r  = tid >> 1;
        const int c0 = (tid & 1) << 5;
        const float* qp = Qg + (size_t)r * DH + c0;
        #pragma unroll
        for (int q = 0; q < 32; q += 4) {
            float4 v = *(const float4*)(qp + q);
            Qt[(c0 + q + 0) * QT_LD + r] = v.x;
            Qt[(c0 + q + 1) * QT_LD + r] = v.y;
            Qt[(c0 + q + 2) * QT_LD + r] = v.z;
            Qt[(c0 + q + 3) * QT_LD + r] = v.w;
        }
    }

    float O[8][4];
    float mrun[8], lrun[8];
    #pragma unroll
    for (int i = 0; i < 8; i++) {
        mrun[i] = -1e30f; lrun[i] = 0.f;
        #pragma unroll
        for (int j = 0; j < 4; j++) O[i][j] = 0.f;
    }
    const float scale2 = 0.125f * 1.4426950408889634f;  // base-2 domain
    const int ktmax = 2 * qt + 1;

    for (int kt = 0; kt <= ktmax; kt++) {
        __syncthreads();
        {
            const int lr = tid >> 2;
            const int c0 = (tid & 3) << 4;
            const float* kp = Kg + (size_t)((kt << 6) + lr) * DH + c0;
            const float* vp = Vg + (size_t)((kt << 6) + lr) * DH + c0;
            #pragma unroll
            for (int q = 0; q < 16; q += 4) {
                float4 kv = *(const float4*)(kp + q);
                Kt[(c0 + q + 0) * KV_LD + lr] = kv.x;
                Kt[(c0 + q + 1) * KV_LD + lr] = kv.y;
                Kt[(c0 + q + 2) * KV_LD + lr] = kv.z;
                Kt[(c0 + q + 3) * KV_LD + lr] = kv.w;
                *(float4*)&Vs[lr * KV_LD + c0 + q] = *(const float4*)(vp + q);
            }
        }
        __syncthreads();

        float s[8][4] = {};
        #pragma unroll 8
        for (int d = 0; d < 64; d++) {
            float q[8];
            *(float4*)&q[0] = *(const float4*)&Qt[d * QT_LD + (ty << 3)];
            *(float4*)&q[4] = *(const float4*)&Qt[d * QT_LD + (ty << 3) + 4];
            float4 kv = *(const float4*)&Kt[d * KV_LD + (tx << 2)];
            #pragma unroll
            for (int i = 0; i < 8; i++) {
                s[i][0] = fmaf(q[i], kv.x, s[i][0]);
                s[i][1] = fmaf(q[i], kv.y, s[i][1]);
                s[i][2] = fmaf(q[i], kv.z, s[i][2]);
                s[i][3] = fmaf(q[i], kv.w, s[i][3]);
            }
        }

        if (kt >= 2 * qt) {
            #pragma unroll
            for (int i = 0; i < 8; i++) {
                const int qg = qb + (ty << 3) + i;
                #pragma unroll
                for (int j = 0; j < 4; j++) {
                    const int kg = (kt << 6) + (tx << 2) + j;
                    s[i][j] = (kg <= qg) ? s[i][j] * scale2 : -1e30f;
                }
            }
        } else {
            #pragma unroll
            for (int i = 0; i < 8; i++)
                #pragma unroll
                for (int j = 0; j < 4; j++) s[i][j] *= scale2;
        }

        #pragma unroll
        for (int i = 0; i < 8; i++) {
            float m = fmaxf(fmaxf(s[i][0], s[i][1]), fmaxf(s[i][2], s[i][3]));
            m = fmaxf(m, __shfl_xor_sync(0xffffffffu, m, 1));
            m = fmaxf(m, __shfl_xor_sync(0xffffffffu, m, 2));
            m = fmaxf(m, __shfl_xor_sync(0xffffffffu, m, 4));
            m = fmaxf(m, __shfl_xor_sync(0xffffffffu, m, 8));
            const float mnew  = fmaxf(mrun[i], m);
            const float alpha = fexp2(mrun[i] - mnew);
            float l = 0.f;
            #pragma unroll
            for (int j = 0; j < 4; j++) {
                s[i][j] = fexp2(s[i][j] - mnew);
                l += s[i][j];
            }
            l += __shfl_xor_sync(0xffffffffu, l, 1);
            l += __shfl_xor_sync(0xffffffffu, l, 2);
            l += __shfl_xor_sync(0xffffffffu, l, 4);
            l += __shfl_xor_sync(0xffffffffu, l, 8);
            lrun[i] = lrun[i] * alpha + l;
            mrun[i] = mnew;
            #pragma unroll
            for (int j = 0; j < 4; j++) O[i][j] *= alpha;
            *(float4*)&Ps[((ty << 3) + i) * KV_LD + (tx << 2)] =
                make_float4(s[i][0], s[i][1], s[i][2], s[i][3]);
        }
        __syncwarp();

        #pragma unroll 2
        for (int k4 = 0; k4 < 64; k4 += 4) {
            float4 p[8];
            #pragma unroll
            for (int i = 0; i < 8; i++)
                p[i] = *(const float4*)&Ps[((ty << 3) + i) * KV_LD + k4];
            #pragma unroll
            for (int t = 0; t < 4; t++) {
                float4 v = *(const float4*)&Vs[(k4 + t) * KV_LD + (tx << 2)];
                #pragma unroll
                for (int i = 0; i < 8; i++) {
                    const float pv = (t == 0) ? p[i].x : (t == 1) ? p[i].y
                                   : (t == 2) ? p[i].z : p[i].w;
                    O[i][0] = fmaf(pv, v.x, O[i][0]);
                    O[i][1] = fmaf(pv, v.y, O[i][1]);
                    O[i][2] = fmaf(pv, v.z, O[i][2]);
                    O[i][3] = fmaf(pv, v.w, O[i][3]);
                }
            }
        }
    }

    // epilogue: normalize, split to bf16 hi/lo, write g_Hh/g_Hl [B,S,D]
    #pragma unroll
    for (int i = 0; i < 8; i++) {
        const float inv = 1.0f / lrun[i];
        const size_t idx = (size_t)(b * SEQ + qb + (ty << 3) + i) * DM
                         + h * DH + (tx << 2);
        bf16 h0, l0, h1, l1, h2, l2, h3, l3;
        bsplit(O[i][0] * inv, h0, l0);
        bsplit(O[i][1] * inv, h1, l1);
        bsplit(O[i][2] * inv, h2, l2);
        bsplit(O[i][3] * inv, h3, l3);
        u32* ph = (u32*)(g_Hh + idx);
        u32* pl = (u32*)(g_Hl + idx);
        ph[0] = bpack(h0, h1); ph[1] = bpack(h2, h3);
        pl[0] = bpack(l0, l1); pl[1] = bpack(l2, l3);
    }
}

// ---------------------------------------------------------------------------
extern "C" void kernel_launch(void* const* d_in, const int* in_sizes, int n_in,
                              void* d_out, int out_size) {
    const float* x  = (const float*)d_in[0];
    const float* Wq = (const float*)d_in[1];
    const float* bq = (const float*)d_in[2];
    const float* Wk = (const float*)d_in[3];
    const float* bk = (const float*)d_in[4];
    const float* Wv = (const float*)d_in[5];
    const float* bv = (const float*)d_in[6];
    const float* Wo = (const float*)d_in[7];
    const float* bo = (const float*)d_in[8];
    float* out = (float*)d_out;

    // 0. one-time splits (in-graph, every replay; cheap)
    split_x_kernel<<<MTOT * DM / 256, 256>>>(x);
    split_w_kernel<<<dim3(DM / 32, DM / 32, 4), 256>>>(Wq, Wk, Wv, Wo);

    // 1. QKV projections (bf16x3 tensor cores)
    cudaFuncSetAttribute(qkv_gemm_kernel,
                         cudaFuncAttributeMaxDynamicSharedMemorySize, GEMM_SMEM);
    qkv_gemm_kernel<<<dim3(DM / 128, MTOT / 128, 3), 256, GEMM_SMEM>>>(bq, bk, bv);

    // 2. causal flash attention
    const size_t smem = (size_t)(64 * QT_LD + 2 * 64 * KV_LD + 128 * KV_LD)
                        * sizeof(float);
    cudaFuncSetAttribute(attn_kernel, cudaFuncAttributeMaxDynamicSharedMemorySize,
                         (int)smem);
    attn_kernel<<<dim3(SEQ / QT, BATCH * NH), 256, smem>>>();

    // 3. output projection (bf16x3 tensor cores)
    cudaFuncSetAttribute(out_gemm_kernel,
                         cudaFuncAttributeMaxDynamicSharedMemorySize, GEMM_SMEM);
    out_gemm_kernel<<<dim3(DM / 128, MTOT / 128), 256, GEMM_SMEM>>>(bo, out);
}

// round 9
// speedup vs baseline: 1.9811x; 1.6706x over previous
#include <cuda_runtime.h>
#include <cuda_bf16.h>
#include <cstdint>

typedef __nv_bfloat16 bf16;
typedef uint32_t u32;

#define BATCH 2
#define SEQ   2048
#define DM    1024
#define NH    16
#define DH    64
#define MTOT  (BATCH * SEQ)   // 4096

#define SCALE2F 0.18033688011112042f   // 0.125 * log2(e)

// GEMM smem: 4 tiles (Ah,Al,Bh,Bl) x double buffer x [128][20] u32
#define TROW 20
#define TBUF (128 * TROW)
#define GEMM_SMEM (4 * 2 * TBUF * 4)

// attention smem layout (bf16 rows padded to 72)
#define QLD  72
#define QLDU 36
#define ATTN_SMEM ((2 * 128 * QLD + 4 * 64 * QLD) * 2)

// ---------------------------------------------------------------------------
// device scratch (allocation-free rule)
// ---------------------------------------------------------------------------
__device__ bf16 g_xh[MTOT * DM], g_xl[MTOT * DM];           // x hi/lo [m][k]
__device__ bf16 g_Wh[4 * DM * DM], g_Wl[4 * DM * DM];       // W^T hi/lo [w][n][k]
__device__ bf16 g_Qh[MTOT * DM], g_Ql[MTOT * DM];           // Q(scaled) [bh][s][d]
__device__ bf16 g_Kh[MTOT * DM], g_Kl[MTOT * DM];           // K [bh][s][d]
__device__ bf16 g_Vth[MTOT * DM], g_Vtl[MTOT * DM];         // V^T [bh][d][s]
__device__ bf16 g_Hh[MTOT * DM], g_Hl[MTOT * DM];           // attn out [m][k]

// ---------------------------------------------------------------------------
// helpers
// ---------------------------------------------------------------------------
__device__ __forceinline__ u32 smaddr(const void* p) {
    return (u32)__cvta_generic_to_shared(p);
}
__device__ __forceinline__ void cpa16(u32 s, const void* g) {
    asm volatile("cp.async.cg.shared.global [%0], [%1], 16;" :: "r"(s), "l"(g));
}
__device__ __forceinline__ void cpa_commit() { asm volatile("cp.async.commit_group;"); }
__device__ __forceinline__ void cpa_wait0()  { asm volatile("cp.async.wait_group 0;"); }

__device__ __forceinline__ void bsplit(float v, bf16& h, bf16& l) {
    h = __float2bfloat16(v);
    l = __float2bfloat16(v - __bfloat162float(h));
}
__device__ __forceinline__ u32 bpack(bf16 a, bf16 b) {
    __nv_bfloat162 t = __halves2bfloat162(a, b);
    return *reinterpret_cast<u32*>(&t);
}
__device__ __forceinline__ void mma_bf16(float d[4], const u32 a[4], const u32 b[2]) {
    asm volatile(
        "mma.sync.aligned.m16n8k16.row.col.f32.bf16.bf16.f32 "
        "{%0,%1,%2,%3}, {%4,%5,%6,%7}, {%8,%9}, {%0,%1,%2,%3};"
        : "+f"(d[0]), "+f"(d[1]), "+f"(d[2]), "+f"(d[3])
        : "r"(a[0]), "r"(a[1]), "r"(a[2]), "r"(a[3]), "r"(b[0]), "r"(b[1]));
}

// fast 2^t on the FMA pipe (t <= ~0), |rel err| ~1e-7
__device__ __forceinline__ float fexp2(float t) {
    t = fmaxf(t, -124.0f);
    float k = t + 12582912.0f;
    int   n = __float_as_int(k) - 0x4B400000;
    float f = t - (k - 12582912.0f);
    float p = 1.5403530393e-4f;
    p = fmaf(p, f, 1.3333558146e-3f);
    p = fmaf(p, f, 9.6181291076e-3f);
    p = fmaf(p, f, 5.5504108665e-2f);
    p = fmaf(p, f, 2.4022650696e-1f);
    p = fmaf(p, f, 6.9314718056e-1f);
    p = fmaf(p, f, 1.0f);
    return __int_as_float(__float_as_int(p) + (n << 23));
}

// ---------------------------------------------------------------------------
// prologue: split x; transpose + split W
// ---------------------------------------------------------------------------
__global__ __launch_bounds__(256)
void split_x_kernel(const float* __restrict__ x) {
    int i = blockIdx.x * 256 + threadIdx.x;
    bf16 h, l; bsplit(x[i], h, l);
    g_xh[i] = h; g_xl[i] = l;
}

__global__ __launch_bounds__(256)
void split_w_kernel(const float* __restrict__ Wq, const float* __restrict__ Wk,
                    const float* __restrict__ Wv, const float* __restrict__ Wo) {
    __shared__ float t[32][33];
    const int z = blockIdx.z;
    const float* W = (z == 0) ? Wq : (z == 1) ? Wk : (z == 2) ? Wv : Wo;
    bf16* oh = g_Wh + (size_t)z * DM * DM;
    bf16* ol = g_Wl + (size_t)z * DM * DM;
    const int k0 = blockIdx.x << 5, n0 = blockIdx.y << 5;
    const int tx = threadIdx.x & 31, ty = threadIdx.x >> 5;
    #pragma unroll
    for (int i = 0; i < 32; i += 8)
        t[ty + i][tx] = W[(size_t)(k0 + ty + i) * DM + n0 + tx];
    __syncthreads();
    #pragma unroll
    for (int i = 0; i < 32; i += 8) {
        bf16 h, l; bsplit(t[tx][ty + i], h, l);
        oh[(size_t)(n0 + ty + i) * DM + k0 + tx] = h;
        ol[(size_t)(n0 + ty + i) * DM + k0 + tx] = l;
    }
}

// ---------------------------------------------------------------------------
// bf16x3 GEMM core (unchanged from R7)
// ---------------------------------------------------------------------------
__device__ __forceinline__ void bgemm_core(const bf16* __restrict__ Ah,
                                           const bf16* __restrict__ Al,
                                           const bf16* __restrict__ Bh,
                                           const bf16* __restrict__ Bl,
                                           int m0, int n0,
                                           float acc[4][4][4], char* sm) {
    u32* AsH = (u32*)sm;
    u32* AsL = AsH + 2 * TBUF;
    u32* BsH = AsL + 2 * TBUF;
    u32* BsL = BsH + 2 * TBUF;

    const int tid  = threadIdx.x;
    const int lane = tid & 31, warp = tid >> 5;
    const int wm = warp & 1, wn = warp >> 1;
    const int g = lane >> 2, tig = lane & 3;
    const int lr = tid >> 1;
    const int lc = (tid & 1) << 3;

    const bf16* pAh = Ah + (size_t)(m0 + lr) * DM + (lc << 1);
    const bf16* pAl = Al + (size_t)(m0 + lr) * DM + (lc << 1);
    const bf16* pBh = Bh + (size_t)(n0 + lr) * DM + (lc << 1);
    const bf16* pBl = Bl + (size_t)(n0 + lr) * DM + (lc << 1);
    const u32 dst0 = lr * TROW + lc;

#define LD_TILE(bufv, koff) do {                                          \
    u32 d_ = (bufv) * TBUF + dst0;                                        \
    cpa16(smaddr(AsH + d_),     pAh + (koff));                            \
    cpa16(smaddr(AsH + d_ + 4), pAh + (koff) + 8);                        \
    cpa16(smaddr(AsL + d_),     pAl + (koff));                            \
    cpa16(smaddr(AsL + d_ + 4), pAl + (koff) + 8);                        \
    cpa16(smaddr(BsH + d_),     pBh + (koff));                            \
    cpa16(smaddr(BsH + d_ + 4), pBh + (koff) + 8);                        \
    cpa16(smaddr(BsL + d_),     pBl + (koff));                            \
    cpa16(smaddr(BsL + d_ + 4), pBl + (koff) + 8);                        \
    cpa_commit(); } while (0)

    LD_TILE(0, 0);
    cpa_wait0();
    __syncthreads();

    int buf = 0;
    for (int kt = 32; kt <= DM; kt += 32) {
        const bool more = (kt < DM);
        if (more) LD_TILE(buf ^ 1, kt);

        #pragma unroll
        for (int ks = 0; ks < 2; ks++) {
            const int kc = ks * 8 + tig;
            u32 bhf[4][2], blf[4][2];
            #pragma unroll
            for (int nt = 0; nt < 4; nt++) {
                const int off = buf * TBUF + (wn * 32 + nt * 8 + g) * TROW;
                bhf[nt][0] = BsH[off + kc];  bhf[nt][1] = BsH[off + kc + 4];
                blf[nt][0] = BsL[off + kc];  blf[nt][1] = BsL[off + kc + 4];
            }
            #pragma unroll
            for (int mt = 0; mt < 4; mt++) {
                const int o1 = buf * TBUF + (wm * 64 + mt * 16 + g) * TROW;
                const int o2 = o1 + 8 * TROW;
                u32 ah[4] = {AsH[o1 + kc], AsH[o2 + kc],
                             AsH[o1 + kc + 4], AsH[o2 + kc + 4]};
                u32 al[4] = {AsL[o1 + kc], AsL[o2 + kc],
                             AsL[o1 + kc + 4], AsL[o2 + kc + 4]};
                #pragma unroll
                for (int nt = 0; nt < 4; nt++) {
                    mma_bf16(acc[mt][nt], ah, bhf[nt]);
                    mma_bf16(acc[mt][nt], al, bhf[nt]);
                    mma_bf16(acc[mt][nt], ah, blf[nt]);
                }
            }
        }
        if (more) {
            cpa_wait0();
            __syncthreads();
            buf ^= 1;
        }
    }
#undef LD_TILE
}

// ---------------------------------------------------------------------------
// QKV projections -> split bf16 Q (scaled), K, V^T
// ---------------------------------------------------------------------------
__global__ __launch_bounds__(256, 2)
void qkv_gemm_kernel(const float* __restrict__ bq, const float* __restrict__ bk,
                     const float* __restrict__ bv) {
    extern __shared__ char sm[];
    const int m0 = blockIdx.y << 7;
    const int n0 = blockIdx.x << 7;
    const int which = blockIdx.z;
    const bf16* Bh = g_Wh + (size_t)which * DM * DM;
    const bf16* Bl = g_Wl + (size_t)which * DM * DM;
    const float* bias = (which == 0) ? bq : (which == 1) ? bk : bv;

    float acc[4][4][4] = {};
    bgemm_core(g_xh, g_xl, Bh, Bl, m0, n0, acc, sm);

    const int lane = threadIdx.x & 31;
    const int warp = threadIdx.x >> 5;
    const int wm = warp & 1, wn = warp >> 1;

    #pragma unroll
    for (int mt = 0; mt < 4; mt++) {
        #pragma unroll
        for (int nt = 0; nt < 4; nt++) {
            const int n = n0 + wn * 32 + nt * 8 + ((lane & 3) << 1);
            const int hd = n >> 6;
            const int d  = n & 63;
            const float bn0 = bias[n], bn1 = bias[n + 1];
            #pragma unroll
            for (int half = 0; half < 2; half++) {
                const int m = m0 + wm * 64 + mt * 16 + (lane >> 2) + half * 8;
                const int b = m >> 11;
                const int s = m & (SEQ - 1);
                const int bhq = (b << 4) + hd;
                float v0 = acc[mt][nt][half * 2 + 0] + bn0;
                float v1 = acc[mt][nt][half * 2 + 1] + bn1;
                if (which == 0) { v0 *= SCALE2F; v1 *= SCALE2F; }
                bf16 h0, l0, h1, l1;
                bsplit(v0, h0, l0);
                bsplit(v1, h1, l1);
                if (which < 2) {
                    bf16* dh_ = (which == 0) ? g_Qh : g_Kh;
                    bf16* dl_ = (which == 0) ? g_Ql : g_Kl;
                    const u32 idx = ((u32)(bhq * SEQ + s) << 5) + (d >> 1);
                    ((u32*)dh_)[idx] = bpack(h0, h1);
                    ((u32*)dl_)[idx] = bpack(l0, l1);
                } else {
                    const size_t base = ((size_t)(bhq * DH + d)) * SEQ + s;
                    g_Vth[base] = h0;        g_Vtl[base] = l0;
                    g_Vth[base + SEQ] = h1;  g_Vtl[base + SEQ] = l1;
                }
            }
        }
    }
}

// ---------------------------------------------------------------------------
// Output projection: out = H @ Wo + bo
// ---------------------------------------------------------------------------
__global__ __launch_bounds__(256, 2)
void out_gemm_kernel(const float* __restrict__ bo, float* __restrict__ out) {
    extern __shared__ char sm[];
    const int m0 = blockIdx.y << 7;
    const int n0 = blockIdx.x << 7;
    const bf16* Bh = g_Wh + (size_t)3 * DM * DM;
    const bf16* Bl = g_Wl + (size_t)3 * DM * DM;

    float acc[4][4][4] = {};
    bgemm_core(g_Hh, g_Hl, Bh, Bl, m0, n0, acc, sm);

    const int lane = threadIdx.x & 31;
    const int warp = threadIdx.x >> 5;
    const int wm = warp & 1, wn = warp >> 1;

    #pragma unroll
    for (int mt = 0; mt < 4; mt++) {
        #pragma unroll
        for (int nt = 0; nt < 4; nt++) {
            const int n = n0 + wn * 32 + nt * 8 + ((lane & 3) << 1);
            const float bn0 = bo[n], bn1 = bo[n + 1];
            #pragma unroll
            for (int half = 0; half < 2; half++) {
                const int m = m0 + wm * 64 + mt * 16 + (lane >> 2) + half * 8;
                float2 v = make_float2(acc[mt][nt][half * 2 + 0] + bn0,
                                       acc[mt][nt][half * 2 + 1] + bn1);
                *(float2*)&out[(size_t)m * DM + n] = v;
            }
        }
    }
}

// ---------------------------------------------------------------------------
// Tensor-core causal flash attention.
// CTA: 128 q-rows x 64-key tiles, 8 warps (warp w owns rows w*16..w*16+15).
// QK^T and PV via mma.m16n8k16 bf16x3; P stays in registers.
// ---------------------------------------------------------------------------
__global__ __launch_bounds__(256, 2)
void attn_kernel() {
    extern __shared__ __align__(16) bf16 smb[];
    bf16* Qh = smb;                    // [128][QLD]
    bf16* Ql = Qh + 128 * QLD;
    bf16* Kh = Ql + 128 * QLD;         // [64][QLD]
    bf16* Kl = Kh + 64 * QLD;
    bf16* Vh = Kl + 64 * QLD;          // V^T [64 d][QLD s]
    bf16* Vl = Vh + 64 * QLD;

    const int qt = gridDim.x - 1 - blockIdx.x;    // heavy tiles first
    const int bh = blockIdx.y;
    const int b  = bh >> 4;
    const int hd = bh & (NH - 1);
    const int qb = qt << 7;

    const int tid = threadIdx.x, lane = tid & 31, warp = tid >> 5;
    const int g = lane >> 2, q4 = lane & 3;

    // async-load Q tile (hi+lo)
    {
        const int r = tid >> 1, c0 = (tid & 1) << 5;
        const size_t go = ((size_t)bh * SEQ + qb + r) * DH + c0;
        u32 dh_ = smaddr(Qh + r * QLD + c0);
        u32 dl_ = smaddr(Ql + r * QLD + c0);
        cpa16(dh_,      g_Qh + go);      cpa16(dh_ + 16, g_Qh + go + 8);
        cpa16(dh_ + 32, g_Qh + go + 16); cpa16(dh_ + 48, g_Qh + go + 24);
        cpa16(dl_,      g_Ql + go);      cpa16(dl_ + 16, g_Ql + go + 8);
        cpa16(dl_ + 32, g_Ql + go + 16); cpa16(dl_ + 48, g_Ql + go + 24);
        cpa_commit();
    }

    float O[8][4] = {};
    float mrun0 = -1e30f, mrun1 = -1e30f, lrun0 = 0.f, lrun1 = 0.f;
    const int r0 = qb + warp * 16 + g;       // rows r0 and r0+8

    const int ktmax = 2 * qt + 1;
    for (int kt = 0; kt <= ktmax; kt++) {
        __syncthreads();
        // async-load K (hi/lo) and V^T (hi/lo) tiles
        {
            const int r = tid >> 2, c0 = (tid & 3) << 4;
            const size_t gk = ((size_t)bh * SEQ + (kt << 6) + r) * DH + c0;
            const size_t gv = ((size_t)bh * DH + r) * SEQ + (kt << 6) + c0;
            u32 a;
            a = smaddr(Kh + r * QLD + c0);
            cpa16(a, g_Kh + gk);  cpa16(a + 16, g_Kh + gk + 8);
            a = smaddr(Kl + r * QLD + c0);
            cpa16(a, g_Kl + gk);  cpa16(a + 16, g_Kl + gk + 8);
            a = smaddr(Vh + r * QLD + c0);
            cpa16(a, g_Vth + gv); cpa16(a + 16, g_Vth + gv + 8);
            a = smaddr(Vl + r * QLD + c0);
            cpa16(a, g_Vtl + gv); cpa16(a + 16, g_Vtl + gv + 8);
            cpa_commit();
        }
        cpa_wait0();
        __syncthreads();

        // ---- S = Q K^T (bf16x3) ----
        float S[8][4];
        #pragma unroll
        for (int nt = 0; nt < 8; nt++) {
            S[nt][0] = 0.f; S[nt][1] = 0.f; S[nt][2] = 0.f; S[nt][3] = 0.f;
        }
        const u32* QhU = (const u32*)Qh;
        const u32* QlU = (const u32*)Ql;
        const u32* KhU = (const u32*)Kh;
        const u32* KlU = (const u32*)Kl;

        #pragma unroll
        for (int kk = 0; kk < 4; kk++) {
            const int ab = (warp * 16 + g) * QLDU + kk * 8 + q4;
            u32 ah[4] = {QhU[ab], QhU[ab + 8 * QLDU],
                         QhU[ab + 4], QhU[ab + 8 * QLDU + 4]};
            u32 al[4] = {QlU[ab], QlU[ab + 8 * QLDU],
                         QlU[ab + 4], QlU[ab + 8 * QLDU + 4]};
            #pragma unroll
            for (int nt = 0; nt < 8; nt++) {
                const int bb = (nt * 8 + g) * QLDU + kk * 8 + q4;
                u32 bhf[2] = {KhU[bb], KhU[bb + 4]};
                u32 blf[2] = {KlU[bb], KlU[bb + 4]};
                mma_bf16(S[nt], ah, bhf);
                mma_bf16(S[nt], al, bhf);
                mma_bf16(S[nt], ah, blf);
            }
        }

        // ---- causal mask (diagonal-overlap tiles only) ----
        if (kt >= 2 * qt) {
            const int cb = (kt << 6) + (q4 << 1);
            #pragma unroll
            for (int nt = 0; nt < 8; nt++) {
                const int c = cb + nt * 8;
                if (c > r0)         S[nt][0] = -1e30f;
                if (c + 1 > r0)     S[nt][1] = -1e30f;
                if (c > r0 + 8)     S[nt][2] = -1e30f;
                if (c + 1 > r0 + 8) S[nt][3] = -1e30f;
            }
        }

        // ---- online softmax (base-2 domain; rows r0, r0+8) ----
        float m0 = S[0][0], m1 = S[0][2];
        #pragma unroll
        for (int nt = 0; nt < 8; nt++) {
            m0 = fmaxf(m0, fmaxf(S[nt][0], S[nt][1]));
            m1 = fmaxf(m1, fmaxf(S[nt][2], S[nt][3]));
        }
        m0 = fmaxf(m0, __shfl_xor_sync(0xffffffffu, m0, 1));
        m0 = fmaxf(m0, __shfl_xor_sync(0xffffffffu, m0, 2));
        m1 = fmaxf(m1, __shfl_xor_sync(0xffffffffu, m1, 1));
        m1 = fmaxf(m1, __shfl_xor_sync(0xffffffffu, m1, 2));
        const float mn0 = fmaxf(mrun0, m0), mn1 = fmaxf(mrun1, m1);
        const float al0 = fexp2(mrun0 - mn0), al1 = fexp2(mrun1 - mn1);
        mrun0 = mn0; mrun1 = mn1;

        float l0 = 0.f, l1 = 0.f;
        #pragma unroll
        for (int nt = 0; nt < 8; nt++) {
            S[nt][0] = fexp2(S[nt][0] - mn0);
            S[nt][1] = fexp2(S[nt][1] - mn0);
            S[nt][2] = fexp2(S[nt][2] - mn1);
            S[nt][3] = fexp2(S[nt][3] - mn1);
            l0 += S[nt][0] + S[nt][1];
            l1 += S[nt][2] + S[nt][3];
        }
        l0 += __shfl_xor_sync(0xffffffffu, l0, 1);
        l0 += __shfl_xor_sync(0xffffffffu, l0, 2);
        l1 += __shfl_xor_sync(0xffffffffu, l1, 1);
        l1 += __shfl_xor_sync(0xffffffffu, l1, 2);
        lrun0 = lrun0 * al0 + l0;
        lrun1 = lrun1 * al1 + l1;
        #pragma unroll
        for (int dt = 0; dt < 8; dt++) {
            O[dt][0] *= al0; O[dt][1] *= al0;
            O[dt][2] *= al1; O[dt][3] *= al1;
        }

        // ---- O += P V (P converts in-register to A-fragments) ----
        const u32* VhU = (const u32*)Vh;
        const u32* VlU = (const u32*)Vl;
        #pragma unroll
        for (int kk = 0; kk < 4; kk++) {
            const int nt0 = kk * 2, nt1 = kk * 2 + 1;
            bf16 p0h, p0l, p1h, p1l, p2h, p2l, p3h, p3l;
            bf16 p4h, p4l, p5h, p5l, p6h, p6l, p7h, p7l;
            bsplit(S[nt0][0], p0h, p0l);  bsplit(S[nt0][1], p1h, p1l);
            bsplit(S[nt0][2], p2h, p2l);  bsplit(S[nt0][3], p3h, p3l);
            bsplit(S[nt1][0], p4h, p4l);  bsplit(S[nt1][1], p5h, p5l);
            bsplit(S[nt1][2], p6h, p6l);  bsplit(S[nt1][3], p7h, p7l);
            u32 pah[4] = {bpack(p0h, p1h), bpack(p2h, p3h),
                          bpack(p4h, p5h), bpack(p6h, p7h)};
            u32 pal[4] = {bpack(p0l, p1l), bpack(p2l, p3l),
                          bpack(p4l, p5l), bpack(p6l, p7l)};
            #pragma unroll
            for (int dt = 0; dt < 8; dt++) {
                const int vb = (dt * 8 + g) * QLDU + kk * 8 + q4;
                u32 vbh[2] = {VhU[vb], VhU[vb + 4]};
                u32 vbl[2] = {VlU[vb], VlU[vb + 4]};
                mma_bf16(O[dt], pah, vbh);
                mma_bf16(O[dt], pal, vbh);
                mma_bf16(O[dt], pah, vbl);
            }
        }
    }

    // ---- epilogue: normalize, split, write g_Hh/g_Hl [B,S,DM] ----
    const float inv0 = 1.0f / lrun0, inv1 = 1.0f / lrun1;
    #pragma unroll
    for (int dt = 0; dt < 8; dt++) {
        const int d = hd * DH + dt * 8 + (q4 << 1);
        {
            bf16 h0, l0, h1, l1;
            bsplit(O[dt][0] * inv0, h0, l0);
            bsplit(O[dt][1] * inv0, h1, l1);
            const u32 idx = ((u32)(b * SEQ + r0) * DM + d) >> 1;
            ((u32*)g_Hh)[idx] = bpack(h0, h1);
            ((u32*)g_Hl)[idx] = bpack(l0, l1);
        }
        {
            bf16 h0, l0, h1, l1;
            bsplit(O[dt][2] * inv1, h0, l0);
            bsplit(O[dt][3] * inv1, h1, l1);
            const u32 idx = ((u32)(b * SEQ + r0 + 8) * DM + d) >> 1;
            ((u32*)g_Hh)[idx] = bpack(h0, h1);
            ((u32*)g_Hl)[idx] = bpack(l0, l1);
        }
    }
}

// ---------------------------------------------------------------------------
extern "C" void kernel_launch(void* const* d_in, const int* in_sizes, int n_in,
                              void* d_out, int out_size) {
    const float* x  = (const float*)d_in[0];
    const float* Wq = (const float*)d_in[1];
    const float* bq = (const float*)d_in[2];
    const float* Wk = (const float*)d_in[3];
    const float* bk = (const float*)d_in[4];
    const float* Wv = (const float*)d_in[5];
    const float* bv = (const float*)d_in[6];
    const float* Wo = (const float*)d_in[7];
    const float* bo = (const float*)d_in[8];
    float* out = (float*)d_out;

    // 0. splits
    split_x_kernel<<<MTOT * DM / 256, 256>>>(x);
    split_w_kernel<<<dim3(DM / 32, DM / 32, 4), 256>>>(Wq, Wk, Wv, Wo);

    // 1. QKV projections
    cudaFuncSetAttribute(qkv_gemm_kernel,
                         cudaFuncAttributeMaxDynamicSharedMemorySize, GEMM_SMEM);
    qkv_gemm_kernel<<<dim3(DM / 128, MTOT / 128, 3), 256, GEMM_SMEM>>>(bq, bk, bv);

    // 2. tensor-core causal flash attention
    cudaFuncSetAttribute(attn_kernel,
                         cudaFuncAttributeMaxDynamicSharedMemorySize, ATTN_SMEM);
    attn_kernel<<<dim3(SEQ / 128, BATCH * NH), 256, ATTN_SMEM>>>();

    // 3. output projection
    cudaFuncSetAttribute(out_gemm_kernel,
                         cudaFuncAttributeMaxDynamicSharedMemorySize, GEMM_SMEM);
    out_gemm_kernel<<<dim3(DM / 128, MTOT / 128), 256, GEMM_SMEM>>>(bo, out);
}